// round 1
// baseline (speedup 1.0000x reference)
#include <cuda_runtime.h>
#include <math.h>

#define DEV_INLINE __device__ __forceinline__

// Problem dims
constexpr int Bc = 2;
constexpr int Lc = 2048;
constexpr int Dc = 1024;
constexpr int Hc = 16;
constexpr int HDc = 64;
constexpr int Mc = Bc * Lc;      // 4096 rows
constexpr int DFc = 4096;        // FFN hidden

// -------- scratch (static device globals; no allocation at runtime) --------
__device__ float g_xn [Mc * Dc];
__device__ float g_yq [Mc * Dc];
__device__ float g_yk [Mc * Dc];
__device__ float g_yv [Mc * Dc];
__device__ float g_q  [Mc * Dc];
__device__ float g_k  [Mc * Dc];
__device__ float g_v  [Mc * Dc];
__device__ float g_k2 [Bc * Hc * Lc];
__device__ float g_att[Mc * Dc];
__device__ float g_o  [Mc * Dc];
__device__ float g_x2 [Mc * Dc];
__device__ float g_ffh[(size_t)Mc * DFc];
__device__ float g_f2 [Mc * Dc];

DEV_INLINE float warp_sum(float v) {
    #pragma unroll
    for (int o = 16; o > 0; o >>= 1) v += __shfl_xor_sync(0xffffffffu, v, o);
    return v;
}

// ---------------- LayerNorm: one block per row of 1024 ----------------
__global__ void ln_kernel(const float* __restrict__ x,
                          const float* __restrict__ g,
                          const float* __restrict__ b,
                          float* __restrict__ y)
{
    __shared__ float red[8];
    int row = blockIdx.x;
    int t = threadIdx.x;                 // 256 threads, 4 floats each
    const float4* xr = (const float4*)(x + (size_t)row * Dc);
    float4 v = xr[t];

    float s = v.x + v.y + v.z + v.w;
    s = warp_sum(s);
    if ((t & 31) == 0) red[t >> 5] = s;
    __syncthreads();
    float tot = 0.f;
    #pragma unroll
    for (int i = 0; i < 8; i++) tot += red[i];
    float mean = tot * (1.0f / Dc);
    __syncthreads();

    float dx = v.x - mean, dy = v.y - mean, dz = v.z - mean, dw = v.w - mean;
    float s2 = dx*dx + dy*dy + dz*dz + dw*dw;
    s2 = warp_sum(s2);
    if ((t & 31) == 0) red[t >> 5] = s2;
    __syncthreads();
    float tot2 = 0.f;
    #pragma unroll
    for (int i = 0; i < 8; i++) tot2 += red[i];
    float rstd = rsqrtf(tot2 * (1.0f / Dc) + 1e-5f);

    float4 gg = ((const float4*)g)[t];
    float4 bb = ((const float4*)b)[t];
    float4 o;
    o.x = dx * rstd * gg.x + bb.x;
    o.y = dy * rstd * gg.y + bb.y;
    o.z = dz * rstd * gg.z + bb.z;
    o.w = dw * rstd * gg.w + bb.w;
    ((float4*)(y + (size_t)row * Dc))[t] = o;
}

// ---------------- residual + Poincare projection over full row (D=1024) ----
__global__ void resproj_kernel(const float* __restrict__ x,
                               const float* __restrict__ add,
                               float* __restrict__ out)
{
    __shared__ float red[8];
    int row = blockIdx.x;
    int t = threadIdx.x;
    float4 a = ((const float4*)(x   + (size_t)row * Dc))[t];
    float4 c = ((const float4*)(add + (size_t)row * Dc))[t];
    float4 v = make_float4(a.x + c.x, a.y + c.y, a.z + c.z, a.w + c.w);

    float s = v.x*v.x + v.y*v.y + v.z*v.z + v.w*v.w;
    s = warp_sum(s);
    if ((t & 31) == 0) red[t >> 5] = s;
    __syncthreads();
    float tot = 0.f;
    #pragma unroll
    for (int i = 0; i < 8; i++) tot += red[i];
    float n = sqrtf(tot);
    const float maxn = 1.0f - 1e-5f;
    float sc = (n > maxn) ? (maxn / n) : 1.0f;

    v.x *= sc; v.y *= sc; v.z *= sc; v.w *= sc;
    ((float4*)(out + (size_t)row * Dc))[t] = v;
}

// ---------------- GEMM: C[M,N] = A[M,K] @ B[N,K]^T + bias, optional GELU ----
// 128x128 tile, BK=16, 256 threads, 8x8 per thread.
template<int EPI>
__global__ __launch_bounds__(256)
void gemm_nt(const float* __restrict__ A, const float* __restrict__ B,
             const float* __restrict__ bias, float* __restrict__ C,
             int M, int N, int K)
{
    __shared__ float As[16][128];
    __shared__ float Bs[16][128];
    int tid = threadIdx.x;
    int bm = blockIdx.y * 128, bn = blockIdx.x * 128;
    int tx = tid & 15, ty = tid >> 4;
    int m0 = ty * 8, n0 = tx * 8;

    float acc[8][8];
    #pragma unroll
    for (int i = 0; i < 8; i++)
        #pragma unroll
        for (int j = 0; j < 8; j++) acc[i][j] = 0.f;

    int lr = tid >> 2;          // 0..63
    int lc = (tid & 3) * 4;     // 0,4,8,12
    const float* Ap = A + (size_t)(bm + lr) * K + lc;
    const float* Bp = B + (size_t)(bn + lr) * K + lc;

    for (int k0 = 0; k0 < K; k0 += 16) {
        #pragma unroll
        for (int s = 0; s < 2; s++) {
            float4 va = *(const float4*)(Ap + (size_t)s * 64 * K + k0);
            int r = lr + s * 64;
            As[lc+0][r] = va.x; As[lc+1][r] = va.y;
            As[lc+2][r] = va.z; As[lc+3][r] = va.w;
            float4 vb = *(const float4*)(Bp + (size_t)s * 64 * K + k0);
            Bs[lc+0][r] = vb.x; Bs[lc+1][r] = vb.y;
            Bs[lc+2][r] = vb.z; Bs[lc+3][r] = vb.w;
        }
        __syncthreads();
        #pragma unroll
        for (int kk = 0; kk < 16; kk++) {
            float a[8], bb[8];
            *(float4*)(a)      = *(const float4*)&As[kk][m0];
            *(float4*)(a + 4)  = *(const float4*)&As[kk][m0 + 4];
            *(float4*)(bb)     = *(const float4*)&Bs[kk][n0];
            *(float4*)(bb + 4) = *(const float4*)&Bs[kk][n0 + 4];
            #pragma unroll
            for (int i = 0; i < 8; i++)
                #pragma unroll
                for (int j = 0; j < 8; j++)
                    acc[i][j] = fmaf(a[i], bb[j], acc[i][j]);
        }
        __syncthreads();
    }

    float bsv[8];
    #pragma unroll
    for (int j = 0; j < 8; j++) bsv[j] = bias[bn + n0 + j];

    #pragma unroll
    for (int i = 0; i < 8; i++) {
        float vrow[8];
        #pragma unroll
        for (int j = 0; j < 8; j++) {
            float v = acc[i][j] + bsv[j];
            if (EPI == 1) v = 0.5f * v * (1.0f + erff(v * 0.70710678118654752f));
            vrow[j] = v;
        }
        float* cp = C + (size_t)(bm + m0 + i) * N + bn + n0;
        *(float4*)(cp)     = *(float4*)(vrow);
        *(float4*)(cp + 4) = *(float4*)(vrow + 4);
    }
}

// ---------------- head split + per-head (hd=64) projection + k2 -------------
// grid = B*L blocks, 512 threads = 16 warps, warp w handles head w.
__global__ void qkv_tr_kernel(const float* __restrict__ yq,
                              const float* __restrict__ yk,
                              const float* __restrict__ yv,
                              float* __restrict__ q, float* __restrict__ k,
                              float* __restrict__ v, float* __restrict__ k2)
{
    int bl = blockIdx.x;             // 0..4095
    int b = bl >> 11;                // / 2048
    int l = bl & 2047;
    int w = threadIdx.x >> 5;        // head
    int lane = threadIdx.x & 31;
    const float maxn = 1.0f - 1e-5f;

    size_t src = (size_t)bl * Dc + w * HDc + lane * 2;
    size_t dst = ((size_t)(b * Hc + w) * Lc + l) * HDc + lane * 2;

    float2 qv = *(const float2*)(yq + src);
    float sq = warp_sum(qv.x*qv.x + qv.y*qv.y);
    float nq = sqrtf(sq);
    float scq = (nq > maxn) ? (maxn / nq) : 1.0f;
    *(float2*)(q + dst) = make_float2(qv.x * scq, qv.y * scq);

    float2 kv = *(const float2*)(yk + src);
    float sk = warp_sum(kv.x*kv.x + kv.y*kv.y);
    float nk = sqrtf(sk);
    float sck = (nk > maxn) ? (maxn / nk) : 1.0f;
    *(float2*)(k + dst) = make_float2(kv.x * sck, kv.y * sck);
    if (lane == 0) k2[(size_t)(b * Hc + w) * Lc + l] = sk * sck * sck;

    *(float2*)(v + dst) = *(const float2*)(yv + src);
}

// ---------------- flash attention --------------------------------------
// logits = (2 q.k - ||k||^2)/temp   (||q||^2 dropped: softmax-invariant)
// BQ=128 queries per CTA, key tiles of 64, hd=64.
// 256 threads; thread owns a 4(row)x8(col) fragment for both S and O.
constexpr int ATT_SMEM_FLOATS = 128*65 + 64*65 + 64*65 + 128*65 + 64;
constexpr int ATT_SMEM = ATT_SMEM_FLOATS * 4;

__global__ __launch_bounds__(256, 2)
void attn_kernel(const float* __restrict__ q, const float* __restrict__ k,
                 const float* __restrict__ v, const float* __restrict__ k2,
                 float* __restrict__ out)
{
    extern __shared__ float sm[];
    float* Qs  = sm;                     // [128][65]
    float* Ks  = Qs + 128 * 65;          // [64][65]
    float* Vs  = Ks + 64 * 65;           // [64][65]
    float* Ps  = Vs + 64 * 65;           // [128][65]
    float* k2s = Ps + 128 * 65;          // [64]

    int qb = blockIdx.x;                 // 0..15
    int bh = blockIdx.y;                 // 0..31
    int tid = threadIdx.x;

    // load Q tile (128 x 64)
    const float* qbase = q + ((size_t)bh * Lc + qb * 128) * HDc;
    #pragma unroll
    for (int it = 0; it < 8; it++) {
        int i = tid + it * 256;          // 0..2047 float4 chunks
        int r = i >> 4, c4 = (i & 15) * 4;
        float4 t = *(const float4*)(qbase + r * HDc + c4);
        Qs[r*65 + c4+0] = t.x; Qs[r*65 + c4+1] = t.y;
        Qs[r*65 + c4+2] = t.z; Qs[r*65 + c4+3] = t.w;
    }

    int trow = tid >> 3, tcol = tid & 7;
    int r0 = trow * 4, c0 = tcol * 8;

    float o_[4][8];
    float m_[4], l_[4];
    #pragma unroll
    for (int i = 0; i < 4; i++) {
        m_[i] = -INFINITY; l_[i] = 0.f;
        #pragma unroll
        for (int j = 0; j < 8; j++) o_[i][j] = 0.f;
    }
    const float invt = 0.125f;  // 1/sqrt(64)

    for (int jb = 0; jb < Lc / 64; jb++) {
        __syncthreads();   // prev iter done reading Ks/Vs/Ps
        const float* kb = k + ((size_t)bh * Lc + jb * 64) * HDc;
        const float* vb = v + ((size_t)bh * Lc + jb * 64) * HDc;
        #pragma unroll
        for (int it = 0; it < 4; it++) {
            int i = tid + it * 256;      // 0..1023 float4 chunks
            int r = i >> 4, c4 = (i & 15) * 4;
            float4 a = *(const float4*)(kb + r * HDc + c4);
            Ks[r*65 + c4+0] = a.x; Ks[r*65 + c4+1] = a.y;
            Ks[r*65 + c4+2] = a.z; Ks[r*65 + c4+3] = a.w;
            float4 bv = *(const float4*)(vb + r * HDc + c4);
            Vs[r*65 + c4+0] = bv.x; Vs[r*65 + c4+1] = bv.y;
            Vs[r*65 + c4+2] = bv.z; Vs[r*65 + c4+3] = bv.w;
        }
        if (tid < 64) k2s[tid] = k2[(size_t)bh * Lc + jb * 64 + tid];
        __syncthreads();

        // S = Q K^T (4x8 fragment per thread)
        float s_[4][8];
        #pragma unroll
        for (int i = 0; i < 4; i++)
            #pragma unroll
            for (int j = 0; j < 8; j++) s_[i][j] = 0.f;

        #pragma unroll 8
        for (int d = 0; d < 64; d++) {
            float aq[4], bk[8];
            #pragma unroll
            for (int i = 0; i < 4; i++) aq[i] = Qs[(r0 + i) * 65 + d];
            #pragma unroll
            for (int j = 0; j < 8; j++) bk[j] = Ks[(c0 + j) * 65 + d];
            #pragma unroll
            for (int i = 0; i < 4; i++)
                #pragma unroll
                for (int j = 0; j < 8; j++)
                    s_[i][j] = fmaf(aq[i], bk[j], s_[i][j]);
        }

        float k2v[8];
        #pragma unroll
        for (int j = 0; j < 8; j++) k2v[j] = k2s[c0 + j];
        #pragma unroll
        for (int i = 0; i < 4; i++)
            #pragma unroll
            for (int j = 0; j < 8; j++)
                s_[i][j] = (2.0f * s_[i][j] - k2v[j]) * invt;

        // online softmax (8-thread groups own a row; reduce via shfl_xor 1,2,4)
        #pragma unroll
        for (int i = 0; i < 4; i++) {
            float rm = s_[i][0];
            #pragma unroll
            for (int j = 1; j < 8; j++) rm = fmaxf(rm, s_[i][j]);
            #pragma unroll
            for (int o = 1; o < 8; o <<= 1)
                rm = fmaxf(rm, __shfl_xor_sync(0xffffffffu, rm, o));
            float mn = fmaxf(m_[i], rm);
            float alpha = __expf(m_[i] - mn);
            float rs = 0.f;
            #pragma unroll
            for (int j = 0; j < 8; j++) {
                float p = __expf(s_[i][j] - mn);
                Ps[(r0 + i) * 65 + c0 + j] = p;
                rs += p;
            }
            #pragma unroll
            for (int o = 1; o < 8; o <<= 1)
                rs += __shfl_xor_sync(0xffffffffu, rs, o);
            l_[i] = l_[i] * alpha + rs;
            m_[i] = mn;
            #pragma unroll
            for (int j = 0; j < 8; j++) o_[i][j] *= alpha;
        }
        __syncthreads();

        // O += P V
        #pragma unroll 8
        for (int c = 0; c < 64; c++) {
            float ap[4], bv[8];
            #pragma unroll
            for (int i = 0; i < 4; i++) ap[i] = Ps[(r0 + i) * 65 + c];
            #pragma unroll
            for (int j = 0; j < 8; j++) bv[j] = Vs[c * 65 + c0 + j];
            #pragma unroll
            for (int i = 0; i < 4; i++)
                #pragma unroll
                for (int j = 0; j < 8; j++)
                    o_[i][j] = fmaf(ap[i], bv[j], o_[i][j]);
        }
    }

    // write out in (b, l, h*64+d) layout for the O-projection GEMM
    int b = bh >> 4, h = bh & 15;
    #pragma unroll
    for (int i = 0; i < 4; i++) {
        float inv = 1.0f / l_[i];
        int row = qb * 128 + r0 + i;
        float* op = out + ((size_t)(b * Lc + row)) * Dc + h * HDc + c0;
        #pragma unroll
        for (int j = 0; j < 8; j++) op[j] = o_[i][j] * inv;
    }
}

// -------------------------------- host ----------------------------------
static float* sym_ptr(const void* sym) {
    void* p = nullptr;
    cudaGetSymbolAddress(&p, sym);
    return (float*)p;
}

extern "C" void kernel_launch(void* const* d_in, const int* in_sizes, int n_in,
                              void* d_out, int out_size)
{
    const float* x   = (const float*)d_in[0];
    const float* wq  = (const float*)d_in[1];
    const float* bq  = (const float*)d_in[2];
    const float* wk  = (const float*)d_in[3];
    const float* bk  = (const float*)d_in[4];
    const float* wv  = (const float*)d_in[5];
    const float* bv  = (const float*)d_in[6];
    const float* wo  = (const float*)d_in[7];
    const float* bo  = (const float*)d_in[8];
    const float* g1  = (const float*)d_in[9];
    const float* b1  = (const float*)d_in[10];
    const float* g2  = (const float*)d_in[11];
    const float* b2  = (const float*)d_in[12];
    const float* w1  = (const float*)d_in[13];
    const float* bf1 = (const float*)d_in[14];
    const float* w2  = (const float*)d_in[15];
    const float* bf2 = (const float*)d_in[16];
    float* out = (float*)d_out;

    float* xn  = sym_ptr(g_xn);
    float* yq  = sym_ptr(g_yq);
    float* yk  = sym_ptr(g_yk);
    float* yv  = sym_ptr(g_yv);
    float* qd  = sym_ptr(g_q);
    float* kd  = sym_ptr(g_k);
    float* vd  = sym_ptr(g_v);
    float* k2d = sym_ptr(g_k2);
    float* att = sym_ptr(g_att);
    float* od  = sym_ptr(g_o);
    float* x2  = sym_ptr(g_x2);
    float* ffh = sym_ptr(g_ffh);
    float* f2  = sym_ptr(g_f2);

    dim3 gProj(Dc / 128, Mc / 128);    // (8, 32)
    dim3 gFfn1(DFc / 128, Mc / 128);   // (32, 32)

    // 1) LN1
    ln_kernel<<<Mc, 256>>>(x, g1, b1, xn);
    // 2) Q,K,V projections
    gemm_nt<0><<<gProj, 256>>>(xn, wq, bq, yq, Mc, Dc, Dc);
    gemm_nt<0><<<gProj, 256>>>(xn, wk, bk, yk, Mc, Dc, Dc);
    gemm_nt<0><<<gProj, 256>>>(xn, wv, bv, yv, Mc, Dc, Dc);
    // 3) head split + Poincare projection + k2
    qkv_tr_kernel<<<Mc, 512>>>(yq, yk, yv, qd, kd, vd, k2d);
    // 4) flash attention
    cudaFuncSetAttribute(attn_kernel, cudaFuncAttributeMaxDynamicSharedMemorySize, ATT_SMEM);
    attn_kernel<<<dim3(Lc / 128, Bc * Hc), 256, ATT_SMEM>>>(qd, kd, vd, k2d, att);
    // 5) O projection
    gemm_nt<0><<<gProj, 256>>>(att, wo, bo, od, Mc, Dc, Dc);
    // 6) residual + project
    resproj_kernel<<<Mc, 256>>>(x, od, x2);
    // 7) LN2
    ln_kernel<<<Mc, 256>>>(x2, g2, b2, xn);
    // 8) FFN1 + exact GELU
    gemm_nt<1><<<gFfn1, 256>>>(xn, w1, bf1, ffh, Mc, DFc, Dc);
    // 9) FFN2
    gemm_nt<0><<<gProj, 256>>>(ffh, w2, bf2, f2, Mc, Dc, DFc);
    // 10) residual + project -> output
    resproj_kernel<<<Mc, 256>>>(x2, f2, out);
}

// round 2
// speedup vs baseline: 1.8053x; 1.8053x over previous
#include <cuda_runtime.h>
#include <math.h>
#include <stdint.h>

#define DEV_INLINE __device__ __forceinline__

// Problem dims
constexpr int Bc = 2;
constexpr int Lc = 2048;
constexpr int Dc = 1024;
constexpr int Hc = 16;
constexpr int HDc = 64;
constexpr int Mc = Bc * Lc;      // 4096 rows
constexpr int DFc = 4096;        // FFN hidden

// -------- scratch (static device globals; no allocation at runtime) --------
__device__ float g_xn [Mc * Dc];
__device__ float g_yq [Mc * Dc];
__device__ float g_yk [Mc * Dc];
__device__ float g_yv [Mc * Dc];
__device__ float g_q  [Mc * Dc];
__device__ float g_k  [Mc * Dc];
__device__ float g_v  [Mc * Dc];
__device__ float g_k2 [Bc * Hc * Lc];
__device__ float g_att[Mc * Dc];
__device__ float g_o  [Mc * Dc];
__device__ float g_x2 [Mc * Dc];
__device__ float g_ffh[(size_t)Mc * DFc];
__device__ float g_f2 [Mc * Dc];

DEV_INLINE float warp_sum(float v) {
    #pragma unroll
    for (int o = 16; o > 0; o >>= 1) v += __shfl_xor_sync(0xffffffffu, v, o);
    return v;
}

DEV_INLINE uint32_t f2tf(float x) {
    uint32_t r;
    asm("cvt.rna.tf32.f32 %0, %1;" : "=r"(r) : "f"(x));
    return r;
}

DEV_INLINE void mma_tf32(float* c, const uint32_t* a, const uint32_t* b) {
    asm volatile(
        "mma.sync.aligned.m16n8k8.row.col.f32.tf32.tf32.f32 "
        "{%0,%1,%2,%3}, {%4,%5,%6,%7}, {%8,%9}, {%0,%1,%2,%3};\n"
        : "+f"(c[0]), "+f"(c[1]), "+f"(c[2]), "+f"(c[3])
        : "r"(a[0]), "r"(a[1]), "r"(a[2]), "r"(a[3]),
          "r"(b[0]), "r"(b[1]));
}

// ---------------- LayerNorm: one block per row of 1024 ----------------
__global__ void ln_kernel(const float* __restrict__ x,
                          const float* __restrict__ g,
                          const float* __restrict__ b,
                          float* __restrict__ y)
{
    __shared__ float red[8];
    int row = blockIdx.x;
    int t = threadIdx.x;                 // 256 threads, 4 floats each
    const float4* xr = (const float4*)(x + (size_t)row * Dc);
    float4 v = xr[t];

    float s = v.x + v.y + v.z + v.w;
    s = warp_sum(s);
    if ((t & 31) == 0) red[t >> 5] = s;
    __syncthreads();
    float tot = 0.f;
    #pragma unroll
    for (int i = 0; i < 8; i++) tot += red[i];
    float mean = tot * (1.0f / Dc);
    __syncthreads();

    float dx = v.x - mean, dy = v.y - mean, dz = v.z - mean, dw = v.w - mean;
    float s2 = dx*dx + dy*dy + dz*dz + dw*dw;
    s2 = warp_sum(s2);
    if ((t & 31) == 0) red[t >> 5] = s2;
    __syncthreads();
    float tot2 = 0.f;
    #pragma unroll
    for (int i = 0; i < 8; i++) tot2 += red[i];
    float rstd = rsqrtf(tot2 * (1.0f / Dc) + 1e-5f);

    float4 gg = ((const float4*)g)[t];
    float4 bb = ((const float4*)b)[t];
    float4 o;
    o.x = dx * rstd * gg.x + bb.x;
    o.y = dy * rstd * gg.y + bb.y;
    o.z = dz * rstd * gg.z + bb.z;
    o.w = dw * rstd * gg.w + bb.w;
    ((float4*)(y + (size_t)row * Dc))[t] = o;
}

// ---------------- residual + Poincare projection over full row (D=1024) ----
__global__ void resproj_kernel(const float* __restrict__ x,
                               const float* __restrict__ add,
                               float* __restrict__ out)
{
    __shared__ float red[8];
    int row = blockIdx.x;
    int t = threadIdx.x;
    float4 a = ((const float4*)(x   + (size_t)row * Dc))[t];
    float4 c = ((const float4*)(add + (size_t)row * Dc))[t];
    float4 v = make_float4(a.x + c.x, a.y + c.y, a.z + c.z, a.w + c.w);

    float s = v.x*v.x + v.y*v.y + v.z*v.z + v.w*v.w;
    s = warp_sum(s);
    if ((t & 31) == 0) red[t >> 5] = s;
    __syncthreads();
    float tot = 0.f;
    #pragma unroll
    for (int i = 0; i < 8; i++) tot += red[i];
    float n = sqrtf(tot);
    const float maxn = 1.0f - 1e-5f;
    float sc = (n > maxn) ? (maxn / n) : 1.0f;

    v.x *= sc; v.y *= sc; v.z *= sc; v.w *= sc;
    ((float4*)(out + (size_t)row * Dc))[t] = v;
}

// ---------------- tf32 tensor-core GEMM --------------------------------
// C[M,N] = A[M,K] @ B[N,K]^T + bias, optional exact GELU.
// CTA tile 128x128, BK=32, 256 threads = 8 warps (4M x 2N),
// warp tile 32x64 = 2(M) x 8(N) m16n8k8 fragments.
// Smem layout [m][k] / [n][k] with ld=36: fragment gathers conflict-free.
constexpr int GLD = 36;

template<int EPI>
__global__ __launch_bounds__(256)
void gemm_tf32(const float* __restrict__ A, const float* __restrict__ B,
               const float* __restrict__ bias, float* __restrict__ C,
               int M, int N, int K)
{
    __shared__ uint32_t As[128 * GLD];
    __shared__ uint32_t Bs[128 * GLD];

    int tid = threadIdx.x;
    int bm = blockIdx.y * 128, bn = blockIdx.x * 128;
    int lane = tid & 31, warp = tid >> 5;
    int wm = (warp & 3) * 32;   // warp row offset
    int wn = (warp >> 2) * 64;  // warp col offset
    int grp = lane >> 2, kq = lane & 3;

    float acc[2][8][4];
    #pragma unroll
    for (int mt = 0; mt < 2; mt++)
        #pragma unroll
        for (int nt = 0; nt < 8; nt++)
            #pragma unroll
            for (int r = 0; r < 4; r++) acc[mt][nt][r] = 0.f;

    int lrow = tid >> 3;          // 0..31 within 128 via +i*32
    int lkc  = (tid & 7) * 4;     // 0,4,...,28

    for (int k0 = 0; k0 < K; k0 += 32) {
        // fill As/Bs: 128 rows x 32 k each; each thread 4 float4 chunks
        #pragma unroll
        for (int i = 0; i < 4; i++) {
            int r = lrow + i * 32;
            float4 va = *(const float4*)(A + (size_t)(bm + r) * K + k0 + lkc);
            uint32_t* ap = &As[r * GLD + lkc];
            ap[0] = f2tf(va.x); ap[1] = f2tf(va.y);
            ap[2] = f2tf(va.z); ap[3] = f2tf(va.w);
            float4 vb = *(const float4*)(B + (size_t)(bn + r) * K + k0 + lkc);
            uint32_t* bp = &Bs[r * GLD + lkc];
            bp[0] = f2tf(vb.x); bp[1] = f2tf(vb.y);
            bp[2] = f2tf(vb.z); bp[3] = f2tf(vb.w);
        }
        __syncthreads();

        #pragma unroll
        for (int kk = 0; kk < 4; kk++) {
            int kb = kk * 8 + kq;
            uint32_t a[2][4], b[8][2];
            #pragma unroll
            for (int mt = 0; mt < 2; mt++) {
                int m = wm + mt * 16 + grp;
                a[mt][0] = As[(m    ) * GLD + kb];
                a[mt][1] = As[(m + 8) * GLD + kb];
                a[mt][2] = As[(m    ) * GLD + kb + 4];
                a[mt][3] = As[(m + 8) * GLD + kb + 4];
            }
            #pragma unroll
            for (int nt = 0; nt < 8; nt++) {
                int n = wn + nt * 8 + grp;
                b[nt][0] = Bs[n * GLD + kb];
                b[nt][1] = Bs[n * GLD + kb + 4];
            }
            #pragma unroll
            for (int mt = 0; mt < 2; mt++)
                #pragma unroll
                for (int nt = 0; nt < 8; nt++)
                    mma_tf32(acc[mt][nt], a[mt], b[nt]);
        }
        __syncthreads();
    }

    // epilogue: c0,c1 -> (row grp, cols kq*2..+1); c2,c3 -> row grp+8
    #pragma unroll
    for (int mt = 0; mt < 2; mt++) {
        int row0 = bm + wm + mt * 16 + grp;
        #pragma unroll
        for (int nt = 0; nt < 8; nt++) {
            int col = bn + wn + nt * 8 + kq * 2;
            float b0 = bias[col], b1 = bias[col + 1];
            float v0 = acc[mt][nt][0] + b0;
            float v1 = acc[mt][nt][1] + b1;
            float v2 = acc[mt][nt][2] + b0;
            float v3 = acc[mt][nt][3] + b1;
            if (EPI == 1) {
                v0 = 0.5f * v0 * (1.0f + erff(v0 * 0.70710678118654752f));
                v1 = 0.5f * v1 * (1.0f + erff(v1 * 0.70710678118654752f));
                v2 = 0.5f * v2 * (1.0f + erff(v2 * 0.70710678118654752f));
                v3 = 0.5f * v3 * (1.0f + erff(v3 * 0.70710678118654752f));
            }
            *(float2*)(C + (size_t)row0 * N + col)       = make_float2(v0, v1);
            *(float2*)(C + (size_t)(row0 + 8) * N + col) = make_float2(v2, v3);
        }
    }
}

// ---------------- head split + per-head (hd=64) projection + k2 -------------
__global__ void qkv_tr_kernel(const float* __restrict__ yq,
                              const float* __restrict__ yk,
                              const float* __restrict__ yv,
                              float* __restrict__ q, float* __restrict__ k,
                              float* __restrict__ v, float* __restrict__ k2)
{
    int bl = blockIdx.x;             // 0..4095
    int b = bl >> 11;                // / 2048
    int l = bl & 2047;
    int w = threadIdx.x >> 5;        // head
    int lane = threadIdx.x & 31;
    const float maxn = 1.0f - 1e-5f;

    size_t src = (size_t)bl * Dc + w * HDc + lane * 2;
    size_t dst = ((size_t)(b * Hc + w) * Lc + l) * HDc + lane * 2;

    float2 qv = *(const float2*)(yq + src);
    float sq = warp_sum(qv.x*qv.x + qv.y*qv.y);
    float nq = sqrtf(sq);
    float scq = (nq > maxn) ? (maxn / nq) : 1.0f;
    *(float2*)(q + dst) = make_float2(qv.x * scq, qv.y * scq);

    float2 kv = *(const float2*)(yk + src);
    float sk = warp_sum(kv.x*kv.x + kv.y*kv.y);
    float nk = sqrtf(sk);
    float sck = (nk > maxn) ? (maxn / nk) : 1.0f;
    *(float2*)(k + dst) = make_float2(kv.x * sck, kv.y * sck);
    if (lane == 0) k2[(size_t)(b * Hc + w) * Lc + l] = sk * sck * sck;

    *(float2*)(v + dst) = *(const float2*)(yv + src);
}

// ---------------- flash attention (FP32 SIMT, unchanged) ----------------
constexpr int ATT_SMEM_FLOATS = 128*65 + 64*65 + 64*65 + 128*65 + 64;
constexpr int ATT_SMEM = ATT_SMEM_FLOATS * 4;

__global__ __launch_bounds__(256, 2)
void attn_kernel(const float* __restrict__ q, const float* __restrict__ k,
                 const float* __restrict__ v, const float* __restrict__ k2,
                 float* __restrict__ out)
{
    extern __shared__ float sm[];
    float* Qs  = sm;                     // [128][65]
    float* Ks  = Qs + 128 * 65;          // [64][65]
    float* Vs  = Ks + 64 * 65;           // [64][65]
    float* Ps  = Vs + 64 * 65;           // [128][65]
    float* k2s = Ps + 128 * 65;          // [64]

    int qb = blockIdx.x;                 // 0..15
    int bh = blockIdx.y;                 // 0..31
    int tid = threadIdx.x;

    const float* qbase = q + ((size_t)bh * Lc + qb * 128) * HDc;
    #pragma unroll
    for (int it = 0; it < 8; it++) {
        int i = tid + it * 256;
        int r = i >> 4, c4 = (i & 15) * 4;
        float4 t = *(const float4*)(qbase + r * HDc + c4);
        Qs[r*65 + c4+0] = t.x; Qs[r*65 + c4+1] = t.y;
        Qs[r*65 + c4+2] = t.z; Qs[r*65 + c4+3] = t.w;
    }

    int trow = tid >> 3, tcol = tid & 7;
    int r0 = trow * 4, c0 = tcol * 8;

    float o_[4][8];
    float m_[4], l_[4];
    #pragma unroll
    for (int i = 0; i < 4; i++) {
        m_[i] = -INFINITY; l_[i] = 0.f;
        #pragma unroll
        for (int j = 0; j < 8; j++) o_[i][j] = 0.f;
    }
    const float invt = 0.125f;

    for (int jb = 0; jb < Lc / 64; jb++) {
        __syncthreads();
        const float* kb = k + ((size_t)bh * Lc + jb * 64) * HDc;
        const float* vb = v + ((size_t)bh * Lc + jb * 64) * HDc;
        #pragma unroll
        for (int it = 0; it < 4; it++) {
            int i = tid + it * 256;
            int r = i >> 4, c4 = (i & 15) * 4;
            float4 a = *(const float4*)(kb + r * HDc + c4);
            Ks[r*65 + c4+0] = a.x; Ks[r*65 + c4+1] = a.y;
            Ks[r*65 + c4+2] = a.z; Ks[r*65 + c4+3] = a.w;
            float4 bv = *(const float4*)(vb + r * HDc + c4);
            Vs[r*65 + c4+0] = bv.x; Vs[r*65 + c4+1] = bv.y;
            Vs[r*65 + c4+2] = bv.z; Vs[r*65 + c4+3] = bv.w;
        }
        if (tid < 64) k2s[tid] = k2[(size_t)bh * Lc + jb * 64 + tid];
        __syncthreads();

        float s_[4][8];
        #pragma unroll
        for (int i = 0; i < 4; i++)
            #pragma unroll
            for (int j = 0; j < 8; j++) s_[i][j] = 0.f;

        #pragma unroll 8
        for (int d = 0; d < 64; d++) {
            float aq[4], bk[8];
            #pragma unroll
            for (int i = 0; i < 4; i++) aq[i] = Qs[(r0 + i) * 65 + d];
            #pragma unroll
            for (int j = 0; j < 8; j++) bk[j] = Ks[(c0 + j) * 65 + d];
            #pragma unroll
            for (int i = 0; i < 4; i++)
                #pragma unroll
                for (int j = 0; j < 8; j++)
                    s_[i][j] = fmaf(aq[i], bk[j], s_[i][j]);
        }

        float k2v[8];
        #pragma unroll
        for (int j = 0; j < 8; j++) k2v[j] = k2s[c0 + j];
        #pragma unroll
        for (int i = 0; i < 4; i++)
            #pragma unroll
            for (int j = 0; j < 8; j++)
                s_[i][j] = (2.0f * s_[i][j] - k2v[j]) * invt;

        #pragma unroll
        for (int i = 0; i < 4; i++) {
            float rm = s_[i][0];
            #pragma unroll
            for (int j = 1; j < 8; j++) rm = fmaxf(rm, s_[i][j]);
            #pragma unroll
            for (int o = 1; o < 8; o <<= 1)
                rm = fmaxf(rm, __shfl_xor_sync(0xffffffffu, rm, o));
            float mn = fmaxf(m_[i], rm);
            float alpha = __expf(m_[i] - mn);
            float rs = 0.f;
            #pragma unroll
            for (int j = 0; j < 8; j++) {
                float p = __expf(s_[i][j] - mn);
                Ps[(r0 + i) * 65 + c0 + j] = p;
                rs += p;
            }
            #pragma unroll
            for (int o = 1; o < 8; o <<= 1)
                rs += __shfl_xor_sync(0xffffffffu, rs, o);
            l_[i] = l_[i] * alpha + rs;
            m_[i] = mn;
            #pragma unroll
            for (int j = 0; j < 8; j++) o_[i][j] *= alpha;
        }
        __syncthreads();

        #pragma unroll 8
        for (int c = 0; c < 64; c++) {
            float ap[4], bv[8];
            #pragma unroll
            for (int i = 0; i < 4; i++) ap[i] = Ps[(r0 + i) * 65 + c];
            #pragma unroll
            for (int j = 0; j < 8; j++) bv[j] = Vs[c * 65 + c0 + j];
            #pragma unroll
            for (int i = 0; i < 4; i++)
                #pragma unroll
                for (int j = 0; j < 8; j++)
                    o_[i][j] = fmaf(ap[i], bv[j], o_[i][j]);
        }
    }

    int b = bh >> 4, h = bh & 15;
    #pragma unroll
    for (int i = 0; i < 4; i++) {
        float inv = 1.0f / l_[i];
        int row = qb * 128 + r0 + i;
        float* op = out + ((size_t)(b * Lc + row)) * Dc + h * HDc + c0;
        #pragma unroll
        for (int j = 0; j < 8; j++) op[j] = o_[i][j] * inv;
    }
}

// -------------------------------- host ----------------------------------
static float* sym_ptr(const void* sym) {
    void* p = nullptr;
    cudaGetSymbolAddress(&p, sym);
    return (float*)p;
}

extern "C" void kernel_launch(void* const* d_in, const int* in_sizes, int n_in,
                              void* d_out, int out_size)
{
    const float* x   = (const float*)d_in[0];
    const float* wq  = (const float*)d_in[1];
    const float* bq  = (const float*)d_in[2];
    const float* wk  = (const float*)d_in[3];
    const float* bk  = (const float*)d_in[4];
    const float* wv  = (const float*)d_in[5];
    const float* bv  = (const float*)d_in[6];
    const float* wo  = (const float*)d_in[7];
    const float* bo  = (const float*)d_in[8];
    const float* g1  = (const float*)d_in[9];
    const float* b1  = (const float*)d_in[10];
    const float* g2  = (const float*)d_in[11];
    const float* b2  = (const float*)d_in[12];
    const float* w1  = (const float*)d_in[13];
    const float* bf1 = (const float*)d_in[14];
    const float* w2  = (const float*)d_in[15];
    const float* bf2 = (const float*)d_in[16];
    float* out = (float*)d_out;

    float* xn  = sym_ptr(g_xn);
    float* yq  = sym_ptr(g_yq);
    float* yk  = sym_ptr(g_yk);
    float* yv  = sym_ptr(g_yv);
    float* qd  = sym_ptr(g_q);
    float* kd  = sym_ptr(g_k);
    float* vd  = sym_ptr(g_v);
    float* k2d = sym_ptr(g_k2);
    float* att = sym_ptr(g_att);
    float* od  = sym_ptr(g_o);
    float* x2  = sym_ptr(g_x2);
    float* ffh = sym_ptr(g_ffh);
    float* f2  = sym_ptr(g_f2);

    dim3 gProj(Dc / 128, Mc / 128);    // (8, 32)
    dim3 gFfn1(DFc / 128, Mc / 128);   // (32, 32)

    // 1) LN1
    ln_kernel<<<Mc, 256>>>(x, g1, b1, xn);
    // 2) Q,K,V projections (tf32 tensor cores)
    gemm_tf32<0><<<gProj, 256>>>(xn, wq, bq, yq, Mc, Dc, Dc);
    gemm_tf32<0><<<gProj, 256>>>(xn, wk, bk, yk, Mc, Dc, Dc);
    gemm_tf32<0><<<gProj, 256>>>(xn, wv, bv, yv, Mc, Dc, Dc);
    // 3) head split + Poincare projection + k2
    qkv_tr_kernel<<<Mc, 512>>>(yq, yk, yv, qd, kd, vd, k2d);
    // 4) flash attention
    cudaFuncSetAttribute(attn_kernel, cudaFuncAttributeMaxDynamicSharedMemorySize, ATT_SMEM);
    attn_kernel<<<dim3(Lc / 128, Bc * Hc), 256, ATT_SMEM>>>(qd, kd, vd, k2d, att);
    // 5) O projection
    gemm_tf32<0><<<gProj, 256>>>(att, wo, bo, od, Mc, Dc, Dc);
    // 6) residual + project
    resproj_kernel<<<Mc, 256>>>(x, od, x2);
    // 7) LN2
    ln_kernel<<<Mc, 256>>>(x2, g2, b2, xn);
    // 8) FFN1 + exact GELU
    gemm_tf32<1><<<gFfn1, 256>>>(xn, w1, bf1, ffh, Mc, DFc, Dc);
    // 9) FFN2
    gemm_tf32<0><<<gProj, 256>>>(ffh, w2, bf2, f2, Mc, Dc, DFc);
    // 10) residual + project -> output
    resproj_kernel<<<Mc, 256>>>(x2, f2, out);
}

// round 3
// speedup vs baseline: 3.2800x; 1.8168x over previous
#include <cuda_runtime.h>
#include <math.h>
#include <stdint.h>

#define DEV_INLINE __device__ __forceinline__

// Problem dims
constexpr int Bc = 2;
constexpr int Lc = 2048;
constexpr int Dc = 1024;
constexpr int Hc = 16;
constexpr int HDc = 64;
constexpr int Mc = Bc * Lc;      // 4096 rows
constexpr int DFc = 4096;        // FFN hidden

// -------- scratch (static device globals; no allocation at runtime) --------
__device__ float g_xn [Mc * Dc];
__device__ float g_yq [Mc * Dc];
__device__ float g_yk [Mc * Dc];
__device__ float g_yv [Mc * Dc];
__device__ float g_q  [Mc * Dc];
__device__ float g_k  [Mc * Dc];
__device__ float g_v  [Mc * Dc];
__device__ float g_k2 [Bc * Hc * Lc];
__device__ float g_att[Mc * Dc];
__device__ float g_o  [Mc * Dc];
__device__ float g_x2 [Mc * Dc];
__device__ float g_ffh[(size_t)Mc * DFc];
__device__ float g_f2 [Mc * Dc];

DEV_INLINE float warp_sum(float v) {
    #pragma unroll
    for (int o = 16; o > 0; o >>= 1) v += __shfl_xor_sync(0xffffffffu, v, o);
    return v;
}

DEV_INLINE uint32_t f2tf(float x) {
    uint32_t r;
    asm("cvt.rna.tf32.f32 %0, %1;" : "=r"(r) : "f"(x));
    return r;
}

DEV_INLINE void mma_tf32(float* c, const uint32_t* a, const uint32_t* b) {
    asm volatile(
        "mma.sync.aligned.m16n8k8.row.col.f32.tf32.tf32.f32 "
        "{%0,%1,%2,%3}, {%4,%5,%6,%7}, {%8,%9}, {%0,%1,%2,%3};\n"
        : "+f"(c[0]), "+f"(c[1]), "+f"(c[2]), "+f"(c[3])
        : "r"(a[0]), "r"(a[1]), "r"(a[2]), "r"(a[3]),
          "r"(b[0]), "r"(b[1]));
}

// ---------------- LayerNorm: one block per row of 1024 ----------------
__global__ void ln_kernel(const float* __restrict__ x,
                          const float* __restrict__ g,
                          const float* __restrict__ b,
                          float* __restrict__ y)
{
    __shared__ float red[8];
    int row = blockIdx.x;
    int t = threadIdx.x;
    const float4* xr = (const float4*)(x + (size_t)row * Dc);
    float4 v = xr[t];

    float s = v.x + v.y + v.z + v.w;
    s = warp_sum(s);
    if ((t & 31) == 0) red[t >> 5] = s;
    __syncthreads();
    float tot = 0.f;
    #pragma unroll
    for (int i = 0; i < 8; i++) tot += red[i];
    float mean = tot * (1.0f / Dc);
    __syncthreads();

    float dx = v.x - mean, dy = v.y - mean, dz = v.z - mean, dw = v.w - mean;
    float s2 = dx*dx + dy*dy + dz*dz + dw*dw;
    s2 = warp_sum(s2);
    if ((t & 31) == 0) red[t >> 5] = s2;
    __syncthreads();
    float tot2 = 0.f;
    #pragma unroll
    for (int i = 0; i < 8; i++) tot2 += red[i];
    float rstd = rsqrtf(tot2 * (1.0f / Dc) + 1e-5f);

    float4 gg = ((const float4*)g)[t];
    float4 bb = ((const float4*)b)[t];
    float4 o;
    o.x = dx * rstd * gg.x + bb.x;
    o.y = dy * rstd * gg.y + bb.y;
    o.z = dz * rstd * gg.z + bb.z;
    o.w = dw * rstd * gg.w + bb.w;
    ((float4*)(y + (size_t)row * Dc))[t] = o;
}

// ---------------- residual + Poincare projection over full row ----------
__global__ void resproj_kernel(const float* __restrict__ x,
                               const float* __restrict__ add,
                               float* __restrict__ out)
{
    __shared__ float red[8];
    int row = blockIdx.x;
    int t = threadIdx.x;
    float4 a = ((const float4*)(x   + (size_t)row * Dc))[t];
    float4 c = ((const float4*)(add + (size_t)row * Dc))[t];
    float4 v = make_float4(a.x + c.x, a.y + c.y, a.z + c.z, a.w + c.w);

    float s = v.x*v.x + v.y*v.y + v.z*v.z + v.w*v.w;
    s = warp_sum(s);
    if ((t & 31) == 0) red[t >> 5] = s;
    __syncthreads();
    float tot = 0.f;
    #pragma unroll
    for (int i = 0; i < 8; i++) tot += red[i];
    float n = sqrtf(tot);
    const float maxn = 1.0f - 1e-5f;
    float sc = (n > maxn) ? (maxn / n) : 1.0f;

    v.x *= sc; v.y *= sc; v.z *= sc; v.w *= sc;
    ((float4*)(out + (size_t)row * Dc))[t] = v;
}

// ---------------- tf32 tensor-core GEMM (unchanged from R2) -------------
constexpr int GLD = 36;

template<int EPI>
__global__ __launch_bounds__(256)
void gemm_tf32(const float* __restrict__ A, const float* __restrict__ B,
               const float* __restrict__ bias, float* __restrict__ C,
               int M, int N, int K)
{
    __shared__ uint32_t As[128 * GLD];
    __shared__ uint32_t Bs[128 * GLD];

    int tid = threadIdx.x;
    int bm = blockIdx.y * 128, bn = blockIdx.x * 128;
    int lane = tid & 31, warp = tid >> 5;
    int wm = (warp & 3) * 32;
    int wn = (warp >> 2) * 64;
    int grp = lane >> 2, kq = lane & 3;

    float acc[2][8][4];
    #pragma unroll
    for (int mt = 0; mt < 2; mt++)
        #pragma unroll
        for (int nt = 0; nt < 8; nt++)
            #pragma unroll
            for (int r = 0; r < 4; r++) acc[mt][nt][r] = 0.f;

    int lrow = tid >> 3;
    int lkc  = (tid & 7) * 4;

    for (int k0 = 0; k0 < K; k0 += 32) {
        #pragma unroll
        for (int i = 0; i < 4; i++) {
            int r = lrow + i * 32;
            float4 va = *(const float4*)(A + (size_t)(bm + r) * K + k0 + lkc);
            uint32_t* ap = &As[r * GLD + lkc];
            ap[0] = f2tf(va.x); ap[1] = f2tf(va.y);
            ap[2] = f2tf(va.z); ap[3] = f2tf(va.w);
            float4 vb = *(const float4*)(B + (size_t)(bn + r) * K + k0 + lkc);
            uint32_t* bp = &Bs[r * GLD + lkc];
            bp[0] = f2tf(vb.x); bp[1] = f2tf(vb.y);
            bp[2] = f2tf(vb.z); bp[3] = f2tf(vb.w);
        }
        __syncthreads();

        #pragma unroll
        for (int kk = 0; kk < 4; kk++) {
            int kb = kk * 8 + kq;
            uint32_t a[2][4], b[8][2];
            #pragma unroll
            for (int mt = 0; mt < 2; mt++) {
                int m = wm + mt * 16 + grp;
                a[mt][0] = As[(m    ) * GLD + kb];
                a[mt][1] = As[(m + 8) * GLD + kb];
                a[mt][2] = As[(m    ) * GLD + kb + 4];
                a[mt][3] = As[(m + 8) * GLD + kb + 4];
            }
            #pragma unroll
            for (int nt = 0; nt < 8; nt++) {
                int n = wn + nt * 8 + grp;
                b[nt][0] = Bs[n * GLD + kb];
                b[nt][1] = Bs[n * GLD + kb + 4];
            }
            #pragma unroll
            for (int mt = 0; mt < 2; mt++)
                #pragma unroll
                for (int nt = 0; nt < 8; nt++)
                    mma_tf32(acc[mt][nt], a[mt], b[nt]);
        }
        __syncthreads();
    }

    #pragma unroll
    for (int mt = 0; mt < 2; mt++) {
        int row0 = bm + wm + mt * 16 + grp;
        #pragma unroll
        for (int nt = 0; nt < 8; nt++) {
            int col = bn + wn + nt * 8 + kq * 2;
            float b0 = bias[col], b1 = bias[col + 1];
            float v0 = acc[mt][nt][0] + b0;
            float v1 = acc[mt][nt][1] + b1;
            float v2 = acc[mt][nt][2] + b0;
            float v3 = acc[mt][nt][3] + b1;
            if (EPI == 1) {
                v0 = 0.5f * v0 * (1.0f + erff(v0 * 0.70710678118654752f));
                v1 = 0.5f * v1 * (1.0f + erff(v1 * 0.70710678118654752f));
                v2 = 0.5f * v2 * (1.0f + erff(v2 * 0.70710678118654752f));
                v3 = 0.5f * v3 * (1.0f + erff(v3 * 0.70710678118654752f));
            }
            *(float2*)(C + (size_t)row0 * N + col)       = make_float2(v0, v1);
            *(float2*)(C + (size_t)(row0 + 8) * N + col) = make_float2(v2, v3);
        }
    }
}

// ---------------- head split + projection + prescaled q/k2 --------------
// q stored pre-scaled by 2/temp = 0.25; k2 pre-scaled by 1/temp = 0.125.
__global__ void qkv_tr_kernel(const float* __restrict__ yq,
                              const float* __restrict__ yk,
                              const float* __restrict__ yv,
                              float* __restrict__ q, float* __restrict__ k,
                              float* __restrict__ v, float* __restrict__ k2)
{
    int bl = blockIdx.x;
    int b = bl >> 11;
    int l = bl & 2047;
    int w = threadIdx.x >> 5;
    int lane = threadIdx.x & 31;
    const float maxn = 1.0f - 1e-5f;

    size_t src = (size_t)bl * Dc + w * HDc + lane * 2;
    size_t dst = ((size_t)(b * Hc + w) * Lc + l) * HDc + lane * 2;

    float2 qv = *(const float2*)(yq + src);
    float sq = warp_sum(qv.x*qv.x + qv.y*qv.y);
    float nq = sqrtf(sq);
    float scq = ((nq > maxn) ? (maxn / nq) : 1.0f) * 0.25f;
    *(float2*)(q + dst) = make_float2(qv.x * scq, qv.y * scq);

    float2 kv = *(const float2*)(yk + src);
    float sk = warp_sum(kv.x*kv.x + kv.y*kv.y);
    float nk = sqrtf(sk);
    float sck = (nk > maxn) ? (maxn / nk) : 1.0f;
    *(float2*)(k + dst) = make_float2(kv.x * sck, kv.y * sck);
    if (lane == 0) k2[(size_t)(b * Hc + w) * Lc + l] = sk * sck * sck * 0.125f;

    *(float2*)(v + dst) = *(const float2*)(yv + src);
}

// ---------------- flash attention, tf32 mma ------------------------------
// logits = q'.k - k2'  (q pre-scaled 2/temp, k2 pre-scaled 1/temp)
// CTA: 128 queries, key tiles of 64, hd=64. 8 warps, warp = 16 rows x 64 cols.
// Q fragments register-resident; Q smem region reused as P buffer.
constexpr int ALD = 68;
constexpr int ATT_SMEM = (128 * ALD + 64 * ALD + 64 * ALD) * 4 + 64 * 4;

__global__ __launch_bounds__(256, 2)
void attn_mma_kernel(const float* __restrict__ q, const float* __restrict__ k,
                     const float* __restrict__ v, const float* __restrict__ k2,
                     float* __restrict__ out)
{
    extern __shared__ uint32_t usm[];
    uint32_t* Qs = usm;                 // [128][ALD], reused as Ps
    uint32_t* Ks = Qs + 128 * ALD;      // [64][ALD]
    uint32_t* Vs = Ks + 64 * ALD;       // [64][ALD]
    float* k2s   = (float*)(Vs + 64 * ALD);  // [64]

    int qb = blockIdx.x, bh = blockIdx.y;
    int tid = threadIdx.x, lane = tid & 31, warp = tid >> 5;
    int wm = warp * 16, grp = lane >> 2, kq = lane & 3;

    // load Q tile (128x64) to smem as tf32
    const float* qbase = q + ((size_t)bh * Lc + qb * 128) * HDc;
    #pragma unroll
    for (int it = 0; it < 8; it++) {
        int idx = tid + it * 256;
        int r = idx >> 4, c4 = (idx & 15) * 4;
        float4 t = *(const float4*)(qbase + r * HDc + c4);
        uint32_t* p = &Qs[r * ALD + c4];
        p[0] = f2tf(t.x); p[1] = f2tf(t.y); p[2] = f2tf(t.z); p[3] = f2tf(t.w);
    }
    __syncthreads();

    // hoist Q fragments to registers (reused for all key tiles)
    uint32_t qf[8][4];
    #pragma unroll
    for (int kk = 0; kk < 8; kk++) {
        int kb = kk * 8 + kq, m = wm + grp;
        qf[kk][0] = Qs[m * ALD + kb];
        qf[kk][1] = Qs[(m + 8) * ALD + kb];
        qf[kk][2] = Qs[m * ALD + kb + 4];
        qf[kk][3] = Qs[(m + 8) * ALD + kb + 4];
    }

    float o[8][4];
    #pragma unroll
    for (int nt = 0; nt < 8; nt++)
        #pragma unroll
        for (int r = 0; r < 4; r++) o[nt][r] = 0.f;
    float m0 = -INFINITY, m1 = -INFINITY, l0 = 0.f, l1 = 0.f;

    for (int jb = 0; jb < Lc / 64; jb++) {
        __syncthreads();   // all warps done with Ks/Vs (and Ps self-owned)
        const float* kb_ = k + ((size_t)bh * Lc + jb * 64) * HDc;
        const float* vb_ = v + ((size_t)bh * Lc + jb * 64) * HDc;
        #pragma unroll
        for (int it = 0; it < 4; it++) {
            int idx = tid + it * 256;
            int r = idx >> 4, c4 = (idx & 15) * 4;
            float4 a = *(const float4*)(kb_ + r * HDc + c4);
            uint32_t* kp = &Ks[r * ALD + c4];
            kp[0] = f2tf(a.x); kp[1] = f2tf(a.y); kp[2] = f2tf(a.z); kp[3] = f2tf(a.w);
            float4 bv = *(const float4*)(vb_ + r * HDc + c4);
            uint32_t* vp = &Vs[r * ALD + c4];
            vp[0] = f2tf(bv.x); vp[1] = f2tf(bv.y); vp[2] = f2tf(bv.z); vp[3] = f2tf(bv.w);
        }
        if (tid < 64) k2s[tid] = k2[(size_t)bh * Lc + jb * 64 + tid];
        __syncthreads();

        // S = Q' K^T
        float s[8][4];
        #pragma unroll
        for (int nt = 0; nt < 8; nt++)
            #pragma unroll
            for (int r = 0; r < 4; r++) s[nt][r] = 0.f;

        #pragma unroll
        for (int kk = 0; kk < 8; kk++) {
            int kb = kk * 8 + kq;
            uint32_t b[8][2];
            #pragma unroll
            for (int nt = 0; nt < 8; nt++) {
                int n = nt * 8 + grp;
                b[nt][0] = Ks[n * ALD + kb];
                b[nt][1] = Ks[n * ALD + kb + 4];
            }
            #pragma unroll
            for (int nt = 0; nt < 8; nt++)
                mma_tf32(s[nt], qf[kk], b[nt]);
        }

        // logits = s - k2'
        #pragma unroll
        for (int nt = 0; nt < 8; nt++) {
            float ka = k2s[nt * 8 + kq * 2];
            float kbv = k2s[nt * 8 + kq * 2 + 1];
            s[nt][0] -= ka; s[nt][1] -= kbv;
            s[nt][2] -= ka; s[nt][3] -= kbv;
        }

        // online softmax (rows grp, grp+8; reduce over quad lanes)
        float rm0 = -INFINITY, rm1 = -INFINITY;
        #pragma unroll
        for (int nt = 0; nt < 8; nt++) {
            rm0 = fmaxf(rm0, fmaxf(s[nt][0], s[nt][1]));
            rm1 = fmaxf(rm1, fmaxf(s[nt][2], s[nt][3]));
        }
        #pragma unroll
        for (int ofs = 1; ofs < 4; ofs <<= 1) {
            rm0 = fmaxf(rm0, __shfl_xor_sync(0xffffffffu, rm0, ofs));
            rm1 = fmaxf(rm1, __shfl_xor_sync(0xffffffffu, rm1, ofs));
        }
        float mn0 = fmaxf(m0, rm0), mn1 = fmaxf(m1, rm1);
        float al0 = __expf(m0 - mn0), al1 = __expf(m1 - mn1);
        float rs0 = 0.f, rs1 = 0.f;

        uint32_t* Ps = Qs;
        int prow = (wm + grp) * ALD + kq * 2;
        #pragma unroll
        for (int nt = 0; nt < 8; nt++) {
            float p0 = __expf(s[nt][0] - mn0);
            float p1 = __expf(s[nt][1] - mn0);
            float p2 = __expf(s[nt][2] - mn1);
            float p3 = __expf(s[nt][3] - mn1);
            rs0 += p0 + p1; rs1 += p2 + p3;
            Ps[prow + nt * 8]                 = f2tf(p0);
            Ps[prow + nt * 8 + 1]             = f2tf(p1);
            Ps[prow + 8 * ALD + nt * 8]       = f2tf(p2);
            Ps[prow + 8 * ALD + nt * 8 + 1]   = f2tf(p3);
        }
        #pragma unroll
        for (int ofs = 1; ofs < 4; ofs <<= 1) {
            rs0 += __shfl_xor_sync(0xffffffffu, rs0, ofs);
            rs1 += __shfl_xor_sync(0xffffffffu, rs1, ofs);
        }
        l0 = l0 * al0 + rs0; m0 = mn0;
        l1 = l1 * al1 + rs1; m1 = mn1;
        #pragma unroll
        for (int nt = 0; nt < 8; nt++) {
            o[nt][0] *= al0; o[nt][1] *= al0;
            o[nt][2] *= al1; o[nt][3] *= al1;
        }
        __syncwarp();

        // O += P V
        #pragma unroll
        for (int kk = 0; kk < 8; kk++) {
            int kb = kk * 8 + kq, m = wm + grp;
            uint32_t a[4];
            a[0] = Ps[m * ALD + kb];
            a[1] = Ps[(m + 8) * ALD + kb];
            a[2] = Ps[m * ALD + kb + 4];
            a[3] = Ps[(m + 8) * ALD + kb + 4];
            uint32_t b[8][2];
            #pragma unroll
            for (int nt = 0; nt < 8; nt++) {
                int n = nt * 8 + grp;
                b[nt][0] = Vs[kb * ALD + n];
                b[nt][1] = Vs[(kb + 4) * ALD + n];
            }
            #pragma unroll
            for (int nt = 0; nt < 8; nt++)
                mma_tf32(o[nt], a, b[nt]);
        }
    }

    // write out in (b, l, h*64+d) layout
    float inv0 = 1.0f / l0, inv1 = 1.0f / l1;
    int b_ = bh >> 4, h = bh & 15;
    int row0 = qb * 128 + wm + grp;
    #pragma unroll
    for (int nt = 0; nt < 8; nt++) {
        int col = h * HDc + nt * 8 + kq * 2;
        *(float2*)(out + ((size_t)(b_ * Lc + row0)) * Dc + col) =
            make_float2(o[nt][0] * inv0, o[nt][1] * inv0);
        *(float2*)(out + ((size_t)(b_ * Lc + row0 + 8)) * Dc + col) =
            make_float2(o[nt][2] * inv1, o[nt][3] * inv1);
    }
}

// -------------------------------- host ----------------------------------
static float* sym_ptr(const void* sym) {
    void* p = nullptr;
    cudaGetSymbolAddress(&p, sym);
    return (float*)p;
}

extern "C" void kernel_launch(void* const* d_in, const int* in_sizes, int n_in,
                              void* d_out, int out_size)
{
    const float* x   = (const float*)d_in[0];
    const float* wq  = (const float*)d_in[1];
    const float* bq  = (const float*)d_in[2];
    const float* wk  = (const float*)d_in[3];
    const float* bk  = (const float*)d_in[4];
    const float* wv  = (const float*)d_in[5];
    const float* bv  = (const float*)d_in[6];
    const float* wo  = (const float*)d_in[7];
    const float* bo  = (const float*)d_in[8];
    const float* g1  = (const float*)d_in[9];
    const float* b1  = (const float*)d_in[10];
    const float* g2  = (const float*)d_in[11];
    const float* b2  = (const float*)d_in[12];
    const float* w1  = (const float*)d_in[13];
    const float* bf1 = (const float*)d_in[14];
    const float* w2  = (const float*)d_in[15];
    const float* bf2 = (const float*)d_in[16];
    float* out = (float*)d_out;

    float* xn  = sym_ptr(g_xn);
    float* yq  = sym_ptr(g_yq);
    float* yk  = sym_ptr(g_yk);
    float* yv  = sym_ptr(g_yv);
    float* qd  = sym_ptr(g_q);
    float* kd  = sym_ptr(g_k);
    float* vd  = sym_ptr(g_v);
    float* k2d = sym_ptr(g_k2);
    float* att = sym_ptr(g_att);
    float* od  = sym_ptr(g_o);
    float* x2  = sym_ptr(g_x2);
    float* ffh = sym_ptr(g_ffh);
    float* f2  = sym_ptr(g_f2);

    dim3 gProj(Dc / 128, Mc / 128);
    dim3 gFfn1(DFc / 128, Mc / 128);

    ln_kernel<<<Mc, 256>>>(x, g1, b1, xn);
    gemm_tf32<0><<<gProj, 256>>>(xn, wq, bq, yq, Mc, Dc, Dc);
    gemm_tf32<0><<<gProj, 256>>>(xn, wk, bk, yk, Mc, Dc, Dc);
    gemm_tf32<0><<<gProj, 256>>>(xn, wv, bv, yv, Mc, Dc, Dc);
    qkv_tr_kernel<<<Mc, 512>>>(yq, yk, yv, qd, kd, vd, k2d);

    cudaFuncSetAttribute(attn_mma_kernel, cudaFuncAttributeMaxDynamicSharedMemorySize, ATT_SMEM);
    attn_mma_kernel<<<dim3(Lc / 128, Bc * Hc), 256, ATT_SMEM>>>(qd, kd, vd, k2d, att);

    gemm_tf32<0><<<gProj, 256>>>(att, wo, bo, od, Mc, Dc, Dc);
    resproj_kernel<<<Mc, 256>>>(x, od, x2);
    ln_kernel<<<Mc, 256>>>(x2, g2, b2, xn);
    gemm_tf32<1><<<gFfn1, 256>>>(xn, w1, bf1, ffh, Mc, DFc, Dc);
    gemm_tf32<0><<<gProj, 256>>>(ffh, w2, bf2, f2, Mc, Dc, DFc);
    resproj_kernel<<<Mc, 256>>>(x2, f2, out);
}